// round 16
// baseline (speedup 1.0000x reference)
#include <cuda_runtime.h>
#include <cuda_fp16.h>
#include <cstdint>

// ---------------------------------------------------------------------------
// WMSA: B=16 H=W=64 C=512, window 8x8 (shift 4), 16 heads x 32
// Full fp16 pipeline (fp32 accum):
//   GEMM1: fp16(x) @ fp16(Wqkv) -> g_qkv fp16 (q pre-scaled), CTA 128x96,
//          3-stage ring, 3 CTAs/SM target (48 accums/thread)
//   attn : S = q k^T ; softmax fp32 ; O = fp16(P) v         (R12 form)
//   GEMM2: fp16(O) @ fp16(Wout) -> fp32 scatter out          (R12 form)
// ---------------------------------------------------------------------------
#define CC     512
#define NQKV   1536
#define NHEAD  16
#define MROWS  65536

__device__ float g_bias[NHEAD * 64 * 64];
__device__ __half g_a[(size_t)MROWS * CC];
__device__ __half g_qkv[(size_t)MROWS * NQKV];
__device__ __half g_o[(size_t)MROWS * CC];
__device__ __half g_wqkv[(size_t)NQKV * CC];
__device__ __half g_wout[(size_t)CC * CC];

// ------------------------------- helpers -----------------------------------
__device__ __forceinline__ uint32_t smem_u32(const void* p) {
    uint32_t a;
    asm("{ .reg .u64 t; cvta.to.shared.u64 t, %1; cvt.u32.u64 %0, t; }"
        : "=r"(a) : "l"(p));
    return a;
}
__device__ __forceinline__ uint32_t pack2h(float a, float b) {
    __half2 h = __floats2half2_rn(a, b);
    return *(uint32_t*)&h;
}

#define LDSM4(r0, r1, r2, r3, addr) \
    asm volatile("ldmatrix.sync.aligned.m8n8.x4.shared.b16 {%0,%1,%2,%3}, [%4];" \
        : "=r"(r0), "=r"(r1), "=r"(r2), "=r"(r3) : "r"(addr))
#define LDSM4T(r0, r1, r2, r3, addr) \
    asm volatile("ldmatrix.sync.aligned.m8n8.x4.trans.shared.b16 {%0,%1,%2,%3}, [%4];" \
        : "=r"(r0), "=r"(r1), "=r"(r2), "=r"(r3) : "r"(addr))

#define MMA16816(d, a, b) \
    asm volatile("mma.sync.aligned.m16n8k16.row.col.f32.f16.f16.f32 " \
        "{%0,%1,%2,%3}, {%4,%5,%6,%7}, {%8,%9}, {%0,%1,%2,%3};" \
        : "+f"((d)[0]), "+f"((d)[1]), "+f"((d)[2]), "+f"((d)[3]) \
        : "r"((a)[0]), "r"((a)[1]), "r"((a)[2]), "r"((a)[3]), \
          "r"((b)[0]), "r"((b)[1]))

#define CPASYNC16(smem, gmem) \
    asm volatile("cp.async.cg.shared.global [%0], [%1], 16;" \
        :: "r"(smem), "l"(gmem) : "memory")
#define CPCOMMIT() asm volatile("cp.async.commit_group;" ::: "memory")
#define CPWAIT(n)  asm volatile("cp.async.wait_group %0;" :: "n"(n) : "memory")

#define QK_SCALE 0.17677669529663687f

// ---------------------------------------------------------------------------
// Kernel 0: relative-position bias table
// ---------------------------------------------------------------------------
__global__ void bias_kernel(const float* __restrict__ rel_pos)
{
    int i = blockIdx.x * blockDim.x + threadIdx.x;
    int head = i >> 12;
    int q = (i >> 6) & 63, k = i & 63;
    int qi = q >> 3, qj = q & 7, ki = k >> 3, kj = k & 7;
    int idx = (qi - ki + 7) * 15 + (qj - kj + 7);
    g_bias[i] = rel_pos[idx * NHEAD + head];
}

// ---------------------------------------------------------------------------
// Kernel 0b: transpose + fp16 round of weights
// ---------------------------------------------------------------------------
__global__ void wround_qkv_kernel(const float* __restrict__ w)
{
    int i = blockIdx.x * blockDim.x + threadIdx.x;
    int n = i >> 9, k = i & 511;
    g_wqkv[i] = __float2half_rn(w[(size_t)k * NQKV + n]);
}
__global__ void wround_out_kernel(const float* __restrict__ w)
{
    int i = blockIdx.x * blockDim.x + threadIdx.x;
    int n = i >> 9, k = i & 511;
    g_wout[i] = __float2half_rn(w[(size_t)k * CC + n]);
}

// ---------------------------------------------------------------------------
// Kernel 0c: shift-gather x + fp16 round
// ---------------------------------------------------------------------------
__global__ __launch_bounds__(256)
void xround_kernel(const float* __restrict__ x)
{
    int g = blockIdx.x * blockDim.x + threadIdx.x;
    int m = g >> 6;
    int ku = (g & 63) * 8;
    int win = m >> 6, t = m & 63;
    int b = win >> 6, whi = (win >> 3) & 7, wwi = win & 7;
    int ph = t >> 3, pw = t & 7;
    int h = (whi * 8 + ph + 4) & 63;
    int w = (wwi * 8 + pw + 4) & 63;
    const float* src = x + ((size_t)((b * 64 + h) * 64 + w)) * CC + ku;
    float4 v0 = *(const float4*)src;
    float4 v1 = *(const float4*)(src + 4);
    uint4 hp;
    hp.x = pack2h(v0.x, v0.y);
    hp.y = pack2h(v0.z, v0.w);
    hp.z = pack2h(v1.x, v1.y);
    hp.w = pack2h(v1.z, v1.w);
    *(uint4*)(g_a + (size_t)m * CC + ku) = hp;
}

// ---------------------------------------------------------------------------
// GEMM1: fp16, CTA 128(M) x 96(N), 8 warps 32x48 tiles (48 accums/thread),
// chunk=32 k, 3-stage ring, one sync per chunk, 3 CTAs/SM.
// ---------------------------------------------------------------------------
#define RSTRIDE 80
#define G1_TBH   10240            // 128 rows * 80
#define G1_STAGE 17920            // (128+96) * 80
#define NSTG     3
#define NCHUNK   16

__global__ __launch_bounds__(256, 3)
void qkv_gemm_kernel(const float* __restrict__ bias)
{
    extern __shared__ __align__(16) char dsa[];
    const uint32_t sb = smem_u32(dsa);

    const int tid  = threadIdx.x;
    const int lane = tid & 31, wid = tid >> 5;
    const int bm   = blockIdx.y;
    const int n0   = blockIdx.x * 96;

    // loader: A rows 0..127 (all threads, 2 units), B rows 0..95 (tid<192)
    const int rl = tid >> 1;
    const int ul = (tid & 1) * 2;
    const __half* ah = g_a + (size_t)(bm * 128 + rl) * CC + ul * 8;
    const bool hasB = (tid < 192);
    const __half* bh = g_wqkv + (size_t)(n0 + (hasB ? rl : 0)) * CC + ul * 8;
    const uint32_t s_a = (uint32_t)rl * RSTRIDE + ul * 16;
    const uint32_t s_b = G1_TBH + (uint32_t)rl * RSTRIDE + ul * 16;

    float acc[2][6][4];
    #pragma unroll
    for (int i = 0; i < 2; i++)
        #pragma unroll
        for (int j = 0; j < 6; j++)
            #pragma unroll
            for (int e = 0; e < 4; e++) acc[i][j][e] = 0.0f;

    const int wm = wid >> 1;   // 0..3 : m (32 rows)
    const int wn = wid & 1;    // 0..1 : n (48 cols)

#define ISSUE(c, stg_off) do {                                                \
    const uint32_t _d = sb + (stg_off);                                       \
    const int _k = (c) * 32;                                                  \
    CPASYNC16(_d + s_a,      ah + _k);                                        \
    CPASYNC16(_d + s_a + 16, ah + _k + 8);                                    \
    if (hasB) {                                                               \
        CPASYNC16(_d + s_b,      bh + _k);                                    \
        CPASYNC16(_d + s_b + 16, bh + _k + 8);                                \
    }                                                                         \
    CPCOMMIT();                                                               \
} while (0)

    ISSUE(0, 0);
    ISSUE(1, G1_STAGE);
    CPWAIT(1);
    __syncthreads();

    uint32_t stg_off = 0;
    for (int c = 0; c < NCHUNK; c++) {
        const uint32_t stg = sb + stg_off;

        #pragma unroll
        for (int k16 = 0; k16 < 2; k16++) {
            uint32_t A[2][4], Bh[3][4];
            const uint32_t a_off =
                (uint32_t)(wm * 32 + (lane & 15)) * RSTRIDE
                + (uint32_t)(k16 * 2 + (lane >> 4)) * 16;
            #pragma unroll
            for (int i = 0; i < 2; i++)
                LDSM4(A[i][0], A[i][1], A[i][2], A[i][3],
                      stg + a_off + i * 16 * RSTRIDE);
            const int mi = lane >> 3;
            const uint32_t b_off =
                (uint32_t)(wn * 48 + ((mi >> 1) << 3) + (lane & 7)) * RSTRIDE
                + (uint32_t)(k16 * 2 + (mi & 1)) * 16;
            #pragma unroll
            for (int jp = 0; jp < 3; jp++)
                LDSM4(Bh[jp][0], Bh[jp][1], Bh[jp][2], Bh[jp][3],
                      stg + G1_TBH + b_off + jp * 16 * RSTRIDE);

            #pragma unroll
            for (int i = 0; i < 2; i++)
                #pragma unroll
                for (int j = 0; j < 6; j++)
                    MMA16816(acc[i][j], A[i], &Bh[j >> 1][(j & 1) * 2]);
        }

        if (c + 2 < NCHUNK) {
            uint32_t nxt = stg_off + 2 * G1_STAGE;
            if (nxt >= NSTG * G1_STAGE) nxt -= NSTG * G1_STAGE;
            ISSUE(c + 2, nxt);
        } else {
            CPCOMMIT();
        }
        CPWAIT(1);
        __syncthreads();

        stg_off += G1_STAGE;
        if (stg_off == NSTG * G1_STAGE) stg_off = 0;
    }
#undef ISSUE

    // ---- epilogue: per-column q-scale (tile may straddle col 512) ----
    #pragma unroll
    for (int i = 0; i < 2; i++) {
        #pragma unroll
        for (int half = 0; half < 2; half++) {
            int m = bm * 128 + wm * 32 + i * 16 + half * 8 + (lane >> 2);
            #pragma unroll
            for (int j = 0; j < 6; j++) {
                int cb = n0 + wn * 48 + j * 8 + (lane & 3) * 2;
                float bx = bias[cb], by = bias[cb + 1];
                float qs = (cb < 512) ? QK_SCALE : 1.0f;
                float vx = (acc[i][j][half * 2 + 0] + bx) * qs;
                float vy = (acc[i][j][half * 2 + 1] + by) * qs;
                *(uint32_t*)(g_qkv + (size_t)m * NQKV + cb) = pack2h(vx, vy);
            }
        }
    }
}

// ---------------------------------------------------------------------------
// GEMM2: fp16, CTA 128x128 (R12 config), 3-stage ring, one sync per chunk.
// ---------------------------------------------------------------------------
#define T_AH    0
#define T_BH    10240
#define STAGE   20480

__global__ __launch_bounds__(256)
void out_gemm_kernel(const float* __restrict__ bias,
                     float* __restrict__ outp)
{
    extern __shared__ __align__(16) char dsa[];
    const uint32_t sb = smem_u32(dsa);

    const int tid  = threadIdx.x;
    const int lane = tid & 31, wid = tid >> 5;
    const int bm   = blockIdx.y;
    const int n0   = blockIdx.x * 128;

    const int r = tid >> 2, u = tid & 3;
    const __half* ah = g_o + (size_t)(bm * 128 + r) * CC + u * 8;
    const __half* bh = g_wout + (size_t)(n0 + r) * CC + u * 8;
    const uint32_t s_a = (uint32_t)r * RSTRIDE + u * 16;
    const uint32_t s_b = (uint32_t)(r + 64) * RSTRIDE + u * 16;
    const size_t rowskip = (size_t)64 * CC;

    float acc[4][4][4];
    #pragma unroll
    for (int i = 0; i < 4; i++)
        #pragma unroll
        for (int j = 0; j < 4; j++)
            #pragma unroll
            for (int e = 0; e < 4; e++) acc[i][j][e] = 0.0f;

    const int wm = wid >> 2;
    const int wn = wid & 3;

#define ISSUE(c, stg_off) do {                                                \
    const uint32_t _d = sb + (stg_off);                                       \
    const int _k = (c) * 32;                                                  \
    CPASYNC16(_d + T_AH + s_a, ah + _k);                                      \
    CPASYNC16(_d + T_AH + s_b, ah + rowskip + _k);                            \
    CPASYNC16(_d + T_BH + s_a, bh + _k);                                      \
    CPASYNC16(_d + T_BH + s_b, bh + rowskip + _k);                            \
    CPCOMMIT();                                                               \
} while (0)

    ISSUE(0, 0);
    ISSUE(1, STAGE);
    CPWAIT(1);
    __syncthreads();

    uint32_t stg_off = 0;
    for (int c = 0; c < NCHUNK; c++) {
        const uint32_t stg = sb + stg_off;

        #pragma unroll
        for (int k16 = 0; k16 < 2; k16++) {
            uint32_t A[4][4], Bh[2][4];
            const uint32_t a_off =
                (uint32_t)(wm * 64 + (lane & 15)) * RSTRIDE
                + (uint32_t)(k16 * 2 + (lane >> 4)) * 16;
            #pragma unroll
            for (int i = 0; i < 4; i++)
                LDSM4(A[i][0], A[i][1], A[i][2], A[i][3],
                      stg + T_AH + a_off + i * 16 * RSTRIDE);
            const int mi = lane >> 3;
            const uint32_t b_off =
                (uint32_t)(wn * 32 + ((mi >> 1) << 3) + (lane & 7)) * RSTRIDE
                + (uint32_t)(k16 * 2 + (mi & 1)) * 16;
            #pragma unroll
            for (int jp = 0; jp < 2; jp++)
                LDSM4(Bh[jp][0], Bh[jp][1], Bh[jp][2], Bh[jp][3],
                      stg + T_BH + b_off + jp * 16 * RSTRIDE);

            #pragma unroll
            for (int i = 0; i < 4; i++)
                #pragma unroll
                for (int j = 0; j < 4; j++)
                    MMA16816(acc[i][j], A[i], &Bh[j >> 1][(j & 1) * 2]);
        }

        if (c + 2 < NCHUNK) {
            uint32_t nxt = stg_off + 2 * STAGE;
            if (nxt >= NSTG * STAGE) nxt -= NSTG * STAGE;
            ISSUE(c + 2, nxt);
        } else {
            CPCOMMIT();
        }
        CPWAIT(1);
        __syncthreads();

        stg_off += STAGE;
        if (stg_off == NSTG * STAGE) stg_off = 0;
    }
#undef ISSUE

    float2 bj4[4];
    #pragma unroll
    for (int j = 0; j < 4; j++)
        bj4[j] = *(const float2*)(bias + n0 + wn * 32 + j * 8 + (lane & 3) * 2);

    #pragma unroll
    for (int i = 0; i < 4; i++) {
        #pragma unroll
        for (int half = 0; half < 2; half++) {
            int m = bm * 128 + wm * 64 + i * 16 + half * 8 + (lane >> 2);
            int win = m >> 6, t = m & 63;
            int b = win >> 6, whi = (win >> 3) & 7, wwi = win & 7;
            int ph = t >> 3, pw = t & 7;
            int ho = (whi * 8 + ph + 4) & 63;
            int wo = (wwi * 8 + pw + 4) & 63;
            float* drow = outp + ((size_t)((b * 64 + ho) * 64 + wo)) * CC;
            #pragma unroll
            for (int j = 0; j < 4; j++) {
                int cb = n0 + wn * 32 + j * 8 + (lane & 3) * 2;
                float2 v;
                v.x = acc[i][j][half * 2 + 0] + bj4[j].x;
                v.y = acc[i][j][half * 2 + 1] + bj4[j].y;
                *(float2*)(drow + cb) = v;
            }
        }
    }
}

// ---------------------------------------------------------------------------
// Tensor-core attention: CTA = 128 thr = 1 window x 8 heads, 3-stage ring,
// one sync per head. (R12)
// ---------------------------------------------------------------------------
#define ARS    80
#define ATILE  5120
#define ASTAGE 15360
#define ANSTG  3
#define NHCTA  8

__global__ __launch_bounds__(128)
void attn_kernel()
{
    extern __shared__ __align__(16) char asmem[];
    const uint32_t sb = smem_u32(asmem);

    const int tid  = threadIdx.x;
    const int lane = tid & 31, w = tid >> 5;
    const int win  = blockIdx.x;
    const int hb   = blockIdx.y * NHCTA;

    const __half* gsrc[6];
    uint32_t sdst[6];
    #pragma unroll
    for (int i = 0; i < 6; i++) {
        int c = tid + i * 128;
        int tile = c >> 8;            // 0=qh 1=kh 2=vh
        int row  = (c >> 2) & 63;
        int unit = c & 3;
        gsrc[i] = g_qkv + (size_t)(win * 64 + row) * NQKV
                  + tile * 512 + hb * 32 + unit * 8;
        sdst[i] = (uint32_t)tile * ATILE + (uint32_t)row * ARS + unit * 16;
    }

    auto issue = [&](int h, uint32_t stoff) {
        #pragma unroll
        for (int i = 0; i < 6; i++)
            CPASYNC16(sb + stoff + sdst[i], gsrc[i] + h * 32);
        CPCOMMIT();
    };

    issue(0, 0);
    issue(1, ASTAGE);
    CPWAIT(1);
    __syncthreads();

    const int rr = lane >> 2;
    const int cc2 = (lane & 3) * 2;

    uint32_t stoff = 0;
    for (int h = 0; h < NHCTA; h++) {
        const uint32_t st  = sb + stoff;
        const uint32_t qhB = st;
        const uint32_t khB = st + ATILE;
        const uint32_t vhB = st + 2 * ATILE;
        const int head = hb + h;

        float sacc[8][4];
        #pragma unroll
        for (int j = 0; j < 8; j++)
            #pragma unroll
            for (int e = 0; e < 4; e++) sacc[j][e] = 0.0f;

        #pragma unroll
        for (int ks = 0; ks < 2; ks++) {
            uint32_t Aq[4];
            const uint32_t aoff =
                (uint32_t)(w * 16 + (lane & 15)) * ARS
                + (uint32_t)((lane >> 4) + ks * 2) * 16;
            LDSM4(Aq[0], Aq[1], Aq[2], Aq[3], qhB + aoff);
            const int mi = lane >> 3;
            #pragma unroll
            for (int jp = 0; jp < 4; jp++) {
                uint32_t Bh[4];
                const uint32_t boff =
                    (uint32_t)(jp * 16 + ((mi >> 1) << 3) + (lane & 7)) * ARS
                    + (uint32_t)((mi & 1) + ks * 2) * 16;
                LDSM4(Bh[0], Bh[1], Bh[2], Bh[3], khB + boff);
                MMA16816(sacc[2*jp],   Aq, &Bh[0]);
                MMA16816(sacc[2*jp+1], Aq, &Bh[2]);
            }
        }

        const float* bp = g_bias + ((size_t)head * 64 + w * 16 + rr) * 64 + cc2;
        float mx0 = -1e30f, mx1 = -1e30f;
        #pragma unroll
        for (int j = 0; j < 8; j++) {
            float2 b0 = *(const float2*)(bp + j * 8);
            float2 b1 = *(const float2*)(bp + 512 + j * 8);
            sacc[j][0] += b0.x; sacc[j][1] += b0.y;
            sacc[j][2] += b1.x; sacc[j][3] += b1.y;
            mx0 = fmaxf(mx0, fmaxf(sacc[j][0], sacc[j][1]));
            mx1 = fmaxf(mx1, fmaxf(sacc[j][2], sacc[j][3]));
        }
        mx0 = fmaxf(mx0, __shfl_xor_sync(0xffffffff, mx0, 1));
        mx0 = fmaxf(mx0, __shfl_xor_sync(0xffffffff, mx0, 2));
        mx1 = fmaxf(mx1, __shfl_xor_sync(0xffffffff, mx1, 1));
        mx1 = fmaxf(mx1, __shfl_xor_sync(0xffffffff, mx1, 2));
        float sum0 = 0.0f, sum1 = 0.0f;
        #pragma unroll
        for (int j = 0; j < 8; j++) {
            sacc[j][0] = __expf(sacc[j][0] - mx0);
            sacc[j][1] = __expf(sacc[j][1] - mx0);
            sacc[j][2] = __expf(sacc[j][2] - mx1);
            sacc[j][3] = __expf(sacc[j][3] - mx1);
            sum0 += sacc[j][0] + sacc[j][1];
            sum1 += sacc[j][2] + sacc[j][3];
        }
        sum0 += __shfl_xor_sync(0xffffffff, sum0, 1);
        sum0 += __shfl_xor_sync(0xffffffff, sum0, 2);
        sum1 += __shfl_xor_sync(0xffffffff, sum1, 1);
        sum1 += __shfl_xor_sync(0xffffffff, sum1, 2);
        const float inv0 = 1.0f / sum0, inv1 = 1.0f / sum1;
        #pragma unroll
        for (int j = 0; j < 8; j++) {
            sacc[j][0] *= inv0; sacc[j][1] *= inv0;
            sacc[j][2] *= inv1; sacc[j][3] *= inv1;
        }

        float oacc[4][4];
        #pragma unroll
        for (int j = 0; j < 4; j++)
            #pragma unroll
            for (int e = 0; e < 4; e++) oacc[j][e] = 0.0f;

        #pragma unroll
        for (int ks = 0; ks < 4; ks++) {
            uint32_t ph[4];
            ph[0] = pack2h(sacc[2*ks][0],   sacc[2*ks][1]);
            ph[1] = pack2h(sacc[2*ks][2],   sacc[2*ks][3]);
            ph[2] = pack2h(sacc[2*ks+1][0], sacc[2*ks+1][1]);
            ph[3] = pack2h(sacc[2*ks+1][2], sacc[2*ks+1][3]);

            const uint32_t vrow = (uint32_t)(ks * 16 + (lane & 7)
                                  + ((lane >> 3) & 1) * 8) * ARS;
            #pragma unroll
            for (int dv = 0; dv < 2; dv++) {
                uint32_t Vh[4];
                const uint32_t voff = vrow
                    + (uint32_t)(dv * 16 + (lane >> 4) * 8) * 2;
                LDSM4T(Vh[0], Vh[1], Vh[2], Vh[3], vhB + voff);
                MMA16816(oacc[2*dv],   ph, &Vh[0]);
                MMA16816(oacc[2*dv+1], ph, &Vh[2]);
            }
        }

        {
            const size_t r0 = (size_t)(win * 64 + w * 16 + rr);
            const int colb = head * 32 + cc2;
            #pragma unroll
            for (int j = 0; j < 4; j++) {
                *(uint32_t*)(g_o + r0 * CC + colb + j * 8)
                    = pack2h(oacc[j][0], oacc[j][1]);
                *(uint32_t*)(g_o + (r0 + 8) * CC + colb + j * 8)
                    = pack2h(oacc[j][2], oacc[j][3]);
            }
        }

        if (h + 2 < NHCTA) {
            uint32_t nxt = stoff + 2 * ASTAGE;
            if (nxt >= ANSTG * ASTAGE) nxt -= ANSTG * ASTAGE;
            issue(h + 2, nxt);
        } else {
            CPCOMMIT();
        }
        CPWAIT(1);
        __syncthreads();

        stoff += ASTAGE;
        if (stoff == ANSTG * ASTAGE) stoff = 0;
    }
}

// ---------------------------------------------------------------------------
// launch (GEMM1 in 4th slot for ncu capture)
// ---------------------------------------------------------------------------
extern "C" void kernel_launch(void* const* d_in, const int* in_sizes, int n_in,
                              void* d_out, int out_size)
{
    const float* x       = (const float*)d_in[0];
    const float* w_qkv   = (const float*)d_in[1];
    const float* b_qkv   = (const float*)d_in[2];
    const float* rel_pos = (const float*)d_in[3];
    const float* w_out   = (const float*)d_in[4];
    const float* b_out   = (const float*)d_in[5];
    float* out = (float*)d_out;

    const int dyn1 = NSTG * G1_STAGE;   // 53760
    cudaFuncSetAttribute(qkv_gemm_kernel,
                         cudaFuncAttributeMaxDynamicSharedMemorySize, dyn1);
    const int dyn2 = NSTG * STAGE;      // 61440
    cudaFuncSetAttribute(out_gemm_kernel,
                         cudaFuncAttributeMaxDynamicSharedMemorySize, dyn2);
    const int adyn = ANSTG * ASTAGE;    // 46080
    cudaFuncSetAttribute(attn_kernel,
                         cudaFuncAttributeMaxDynamicSharedMemorySize, adyn);

    xround_kernel<<<(MROWS * 64) / 256, 256>>>(x);
    wround_qkv_kernel<<<(NQKV * CC) / 256, 256>>>(w_qkv);
    wround_out_kernel<<<(CC * CC) / 256, 256>>>(w_out);
    qkv_gemm_kernel<<<dim3(NQKV / 96, MROWS / 128), 256, dyn1>>>(b_qkv);
    bias_kernel<<<64, 1024>>>(rel_pos);
    attn_kernel<<<dim3(1024, NHEAD / NHCTA), 128, adyn>>>();
    out_gemm_kernel<<<dim3(CC / 128, MROWS / 128), 256, dyn2>>>(b_out, out);
}

// round 17
// speedup vs baseline: 1.0649x; 1.0649x over previous
#include <cuda_runtime.h>
#include <cuda_fp16.h>
#include <cstdint>

// ---------------------------------------------------------------------------
// WMSA: B=16 H=W=64 C=512, window 8x8 (shift 4), 16 heads x 32
// Full fp16 pipeline (fp32 accum):
//   pre  : ONE fused kernel: shift-gather+round x, round/transpose weights,
//          build bias table
//   GEMM1: fp16(x) @ fp16(Wqkv) -> g_qkv fp16 (q pre-scaled)   [R12 config]
//   attn : S = q k^T ; softmax fp32 ; O = fp16(P) v            [R12 config]
//   GEMM2: fp16(O) @ fp16(Wout) -> fp32 scatter out            [R12 config]
// ---------------------------------------------------------------------------
#define CC     512
#define NQKV   1536
#define NHEAD  16
#define MROWS  65536

__device__ float g_bias[NHEAD * 64 * 64];
__device__ __half g_a[(size_t)MROWS * CC];
__device__ __half g_qkv[(size_t)MROWS * NQKV];
__device__ __half g_o[(size_t)MROWS * CC];
__device__ __half g_wqkv[(size_t)NQKV * CC];
__device__ __half g_wout[(size_t)CC * CC];

// ------------------------------- helpers -----------------------------------
__device__ __forceinline__ uint32_t smem_u32(const void* p) {
    uint32_t a;
    asm("{ .reg .u64 t; cvta.to.shared.u64 t, %1; cvt.u32.u64 %0, t; }"
        : "=r"(a) : "l"(p));
    return a;
}
__device__ __forceinline__ uint32_t pack2h(float a, float b) {
    __half2 h = __floats2half2_rn(a, b);
    return *(uint32_t*)&h;
}

#define LDSM4(r0, r1, r2, r3, addr) \
    asm volatile("ldmatrix.sync.aligned.m8n8.x4.shared.b16 {%0,%1,%2,%3}, [%4];" \
        : "=r"(r0), "=r"(r1), "=r"(r2), "=r"(r3) : "r"(addr))
#define LDSM4T(r0, r1, r2, r3, addr) \
    asm volatile("ldmatrix.sync.aligned.m8n8.x4.trans.shared.b16 {%0,%1,%2,%3}, [%4];" \
        : "=r"(r0), "=r"(r1), "=r"(r2), "=r"(r3) : "r"(addr))

#define MMA16816(d, a, b) \
    asm volatile("mma.sync.aligned.m16n8k16.row.col.f32.f16.f16.f32 " \
        "{%0,%1,%2,%3}, {%4,%5,%6,%7}, {%8,%9}, {%0,%1,%2,%3};" \
        : "+f"((d)[0]), "+f"((d)[1]), "+f"((d)[2]), "+f"((d)[3]) \
        : "r"((a)[0]), "r"((a)[1]), "r"((a)[2]), "r"((a)[3]), \
          "r"((b)[0]), "r"((b)[1]))

#define CPASYNC16(smem, gmem) \
    asm volatile("cp.async.cg.shared.global [%0], [%1], 16;" \
        :: "r"(smem), "l"(gmem) : "memory")
#define CPCOMMIT() asm volatile("cp.async.commit_group;" ::: "memory")
#define CPWAIT(n)  asm volatile("cp.async.wait_group %0;" :: "n"(n) : "memory")

#define QK_SCALE 0.17677669529663687f

// ---------------------------------------------------------------------------
// Fused pre-pass: block ranges
//   [0, 16384)            : xround   (shift-gather x -> g_a fp16)
//   [16384, 19456)        : wround_qkv (transpose+round)
//   [19456, 20480)        : wround_out (transpose+round)
//   [20480, 20736)        : bias table
// ---------------------------------------------------------------------------
#define PRE_X   16384
#define PRE_WQ  (PRE_X + 3072)
#define PRE_WO  (PRE_WQ + 1024)
#define PRE_END (PRE_WO + 256)

__global__ __launch_bounds__(256)
void pre_kernel(const float* __restrict__ x,
                const float* __restrict__ w_qkv,
                const float* __restrict__ w_out,
                const float* __restrict__ rel_pos)
{
    const int blk = blockIdx.x;
    if (blk < PRE_X) {
        int g = blk * 256 + threadIdx.x;
        int m = g >> 6;
        int ku = (g & 63) * 8;
        int win = m >> 6, t = m & 63;
        int b = win >> 6, whi = (win >> 3) & 7, wwi = win & 7;
        int ph = t >> 3, pw = t & 7;
        int h = (whi * 8 + ph + 4) & 63;
        int w = (wwi * 8 + pw + 4) & 63;
        const float* src = x + ((size_t)((b * 64 + h) * 64 + w)) * CC + ku;
        float4 v0 = *(const float4*)src;
        float4 v1 = *(const float4*)(src + 4);
        uint4 hp;
        hp.x = pack2h(v0.x, v0.y);
        hp.y = pack2h(v0.z, v0.w);
        hp.z = pack2h(v1.x, v1.y);
        hp.w = pack2h(v1.z, v1.w);
        *(uint4*)(g_a + (size_t)m * CC + ku) = hp;
    } else if (blk < PRE_WQ) {
        int i = (blk - PRE_X) * 256 + threadIdx.x;     // NQKV*512
        int n = i >> 9, k = i & 511;
        g_wqkv[i] = __float2half_rn(w_qkv[(size_t)k * NQKV + n]);
    } else if (blk < PRE_WO) {
        int i = (blk - PRE_WQ) * 256 + threadIdx.x;    // 512*512
        int n = i >> 9, k = i & 511;
        g_wout[i] = __float2half_rn(w_out[(size_t)k * CC + n]);
    } else {
        int i = (blk - PRE_WO) * 256 + threadIdx.x;    // 65536
        int head = i >> 12;
        int q = (i >> 6) & 63, k = i & 63;
        int qi = q >> 3, qj = q & 7, ki = k >> 3, kj = k & 7;
        int idx = (qi - ki + 7) * 15 + (qj - kj + 7);
        g_bias[i] = rel_pos[idx * NHEAD + head];
    }
}

// ---------------------------------------------------------------------------
// fp16 single-term GEMM (R12): CTA 128x128, 8 warps 64x32 tiles, chunk=32 k,
// 3-stage ring, one sync per chunk.
//   MODE 0: A = g_a, C -> g_qkv fp16 (q cols pre-scaled)
//   MODE 1: A = g_o, C -> scatter d_out fp32 (reverse shift)
// ---------------------------------------------------------------------------
#define RSTRIDE 80
#define T_AH    0
#define T_BH    10240
#define STAGE   20480
#define NSTG    3
#define NCHUNK  16

template<int MODE>
__global__ __launch_bounds__(256)
void mma_gemm_kernel(const float* __restrict__ bias,
                     float* __restrict__ outp)
{
    extern __shared__ __align__(16) char dsa[];
    const uint32_t sb = smem_u32(dsa);

    const int tid  = threadIdx.x;
    const int lane = tid & 31, wid = tid >> 5;
    const int bm   = blockIdx.y;
    const int n0   = blockIdx.x * 128;

    const int r = tid >> 2, u = tid & 3;
    const __half* ah = (MODE == 0 ? g_a : g_o)
                       + (size_t)(bm * 128 + r) * CC + u * 8;
    const __half* bh = (MODE == 0 ? g_wqkv : g_wout)
                       + (size_t)(n0 + r) * CC + u * 8;
    const uint32_t s_a = (uint32_t)r * RSTRIDE + u * 16;
    const uint32_t s_b = (uint32_t)(r + 64) * RSTRIDE + u * 16;
    const size_t rowskip = (size_t)64 * CC;

    float acc[4][4][4];
    #pragma unroll
    for (int i = 0; i < 4; i++)
        #pragma unroll
        for (int j = 0; j < 4; j++)
            #pragma unroll
            for (int e = 0; e < 4; e++) acc[i][j][e] = 0.0f;

    const int wm = wid >> 2;
    const int wn = wid & 3;

#define ISSUE(c, stg_off) do {                                                \
    const uint32_t _d = sb + (stg_off);                                       \
    const int _k = (c) * 32;                                                  \
    CPASYNC16(_d + T_AH + s_a, ah + _k);                                      \
    CPASYNC16(_d + T_AH + s_b, ah + rowskip + _k);                            \
    CPASYNC16(_d + T_BH + s_a, bh + _k);                                      \
    CPASYNC16(_d + T_BH + s_b, bh + rowskip + _k);                            \
    CPCOMMIT();                                                               \
} while (0)

    ISSUE(0, 0);
    ISSUE(1, STAGE);
    CPWAIT(1);
    __syncthreads();

    uint32_t stg_off = 0;
    for (int c = 0; c < NCHUNK; c++) {
        const uint32_t stg = sb + stg_off;

        #pragma unroll
        for (int k16 = 0; k16 < 2; k16++) {
            uint32_t A[4][4], Bh[2][4];
            const uint32_t a_off =
                (uint32_t)(wm * 64 + (lane & 15)) * RSTRIDE
                + (uint32_t)(k16 * 2 + (lane >> 4)) * 16;
            #pragma unroll
            for (int i = 0; i < 4; i++)
                LDSM4(A[i][0], A[i][1], A[i][2], A[i][3],
                      stg + T_AH + a_off + i * 16 * RSTRIDE);
            const int mi = lane >> 3;
            const uint32_t b_off =
                (uint32_t)(wn * 32 + ((mi >> 1) << 3) + (lane & 7)) * RSTRIDE
                + (uint32_t)(k16 * 2 + (mi & 1)) * 16;
            #pragma unroll
            for (int jp = 0; jp < 2; jp++)
                LDSM4(Bh[jp][0], Bh[jp][1], Bh[jp][2], Bh[jp][3],
                      stg + T_BH + b_off + jp * 16 * RSTRIDE);

            #pragma unroll
            for (int i = 0; i < 4; i++)
                #pragma unroll
                for (int j = 0; j < 4; j++)
                    MMA16816(acc[i][j], A[i], &Bh[j >> 1][(j & 1) * 2]);
        }

        if (c + 2 < NCHUNK) {
            uint32_t nxt = stg_off + 2 * STAGE;
            if (nxt >= NSTG * STAGE) nxt -= NSTG * STAGE;
            ISSUE(c + 2, nxt);
        } else {
            CPCOMMIT();
        }
        CPWAIT(1);
        __syncthreads();

        stg_off += STAGE;
        if (stg_off == NSTG * STAGE) stg_off = 0;
    }
#undef ISSUE

    // ---- epilogue ----
    float2 bj4[4];
    #pragma unroll
    for (int j = 0; j < 4; j++)
        bj4[j] = *(const float2*)(bias + n0 + wn * 32 + j * 8 + (lane & 3) * 2);

    const float qs = (MODE == 0 && n0 < 512) ? QK_SCALE : 1.0f;

    #pragma unroll
    for (int i = 0; i < 4; i++) {
        #pragma unroll
        for (int half = 0; half < 2; half++) {
            int m = bm * 128 + wm * 64 + i * 16 + half * 8 + (lane >> 2);
            #pragma unroll
            for (int j = 0; j < 4; j++) {
                int cb = n0 + wn * 32 + j * 8 + (lane & 3) * 2;
                float vx = (acc[i][j][half * 2 + 0] + bj4[j].x) * qs;
                float vy = (acc[i][j][half * 2 + 1] + bj4[j].y) * qs;
                if (MODE == 0) {
                    *(uint32_t*)(g_qkv + (size_t)m * NQKV + cb) = pack2h(vx, vy);
                } else {
                    int win = m >> 6, t = m & 63;
                    int b = win >> 6, whi = (win >> 3) & 7, wwi = win & 7;
                    int ph = t >> 3, pw = t & 7;
                    int ho = (whi * 8 + ph + 4) & 63;
                    int wo = (wwi * 8 + pw + 4) & 63;
                    float* dst = outp + ((size_t)((b * 64 + ho) * 64 + wo)) * CC + cb;
                    float2 v; v.x = vx; v.y = vy;
                    *(float2*)dst = v;
                }
            }
        }
    }
}

// ---------------------------------------------------------------------------
// Tensor-core attention (R12): CTA = 128 thr = 1 window x 8 heads,
// 3-stage ring, one sync per head.
// ---------------------------------------------------------------------------
#define ARS    80
#define ATILE  5120
#define ASTAGE 15360
#define ANSTG  3
#define NHCTA  8

__global__ __launch_bounds__(128)
void attn_kernel()
{
    extern __shared__ __align__(16) char asmem[];
    const uint32_t sb = smem_u32(asmem);

    const int tid  = threadIdx.x;
    const int lane = tid & 31, w = tid >> 5;
    const int win  = blockIdx.x;
    const int hb   = blockIdx.y * NHCTA;

    const __half* gsrc[6];
    uint32_t sdst[6];
    #pragma unroll
    for (int i = 0; i < 6; i++) {
        int c = tid + i * 128;
        int tile = c >> 8;            // 0=qh 1=kh 2=vh
        int row  = (c >> 2) & 63;
        int unit = c & 3;
        gsrc[i] = g_qkv + (size_t)(win * 64 + row) * NQKV
                  + tile * 512 + hb * 32 + unit * 8;
        sdst[i] = (uint32_t)tile * ATILE + (uint32_t)row * ARS + unit * 16;
    }

    auto issue = [&](int h, uint32_t stoff) {
        #pragma unroll
        for (int i = 0; i < 6; i++)
            CPASYNC16(sb + stoff + sdst[i], gsrc[i] + h * 32);
        CPCOMMIT();
    };

    issue(0, 0);
    issue(1, ASTAGE);
    CPWAIT(1);
    __syncthreads();

    const int rr = lane >> 2;
    const int cc2 = (lane & 3) * 2;

    uint32_t stoff = 0;
    for (int h = 0; h < NHCTA; h++) {
        const uint32_t st  = sb + stoff;
        const uint32_t qhB = st;
        const uint32_t khB = st + ATILE;
        const uint32_t vhB = st + 2 * ATILE;
        const int head = hb + h;

        float sacc[8][4];
        #pragma unroll
        for (int j = 0; j < 8; j++)
            #pragma unroll
            for (int e = 0; e < 4; e++) sacc[j][e] = 0.0f;

        #pragma unroll
        for (int ks = 0; ks < 2; ks++) {
            uint32_t Aq[4];
            const uint32_t aoff =
                (uint32_t)(w * 16 + (lane & 15)) * ARS
                + (uint32_t)((lane >> 4) + ks * 2) * 16;
            LDSM4(Aq[0], Aq[1], Aq[2], Aq[3], qhB + aoff);
            const int mi = lane >> 3;
            #pragma unroll
            for (int jp = 0; jp < 4; jp++) {
                uint32_t Bh[4];
                const uint32_t boff =
                    (uint32_t)(jp * 16 + ((mi >> 1) << 3) + (lane & 7)) * ARS
                    + (uint32_t)((mi & 1) + ks * 2) * 16;
                LDSM4(Bh[0], Bh[1], Bh[2], Bh[3], khB + boff);
                MMA16816(sacc[2*jp],   Aq, &Bh[0]);
                MMA16816(sacc[2*jp+1], Aq, &Bh[2]);
            }
        }

        const float* bp = g_bias + ((size_t)head * 64 + w * 16 + rr) * 64 + cc2;
        float mx0 = -1e30f, mx1 = -1e30f;
        #pragma unroll
        for (int j = 0; j < 8; j++) {
            float2 b0 = *(const float2*)(bp + j * 8);
            float2 b1 = *(const float2*)(bp + 512 + j * 8);
            sacc[j][0] += b0.x; sacc[j][1] += b0.y;
            sacc[j][2] += b1.x; sacc[j][3] += b1.y;
            mx0 = fmaxf(mx0, fmaxf(sacc[j][0], sacc[j][1]));
            mx1 = fmaxf(mx1, fmaxf(sacc[j][2], sacc[j][3]));
        }
        mx0 = fmaxf(mx0, __shfl_xor_sync(0xffffffff, mx0, 1));
        mx0 = fmaxf(mx0, __shfl_xor_sync(0xffffffff, mx0, 2));
        mx1 = fmaxf(mx1, __shfl_xor_sync(0xffffffff, mx1, 1));
        mx1 = fmaxf(mx1, __shfl_xor_sync(0xffffffff, mx1, 2));
        float sum0 = 0.0f, sum1 = 0.0f;
        #pragma unroll
        for (int j = 0; j < 8; j++) {
            sacc[j][0] = __expf(sacc[j][0] - mx0);
            sacc[j][1] = __expf(sacc[j][1] - mx0);
            sacc[j][2] = __expf(sacc[j][2] - mx1);
            sacc[j][3] = __expf(sacc[j][3] - mx1);
            sum0 += sacc[j][0] + sacc[j][1];
            sum1 += sacc[j][2] + sacc[j][3];
        }
        sum0 += __shfl_xor_sync(0xffffffff, sum0, 1);
        sum0 += __shfl_xor_sync(0xffffffff, sum0, 2);
        sum1 += __shfl_xor_sync(0xffffffff, sum1, 1);
        sum1 += __shfl_xor_sync(0xffffffff, sum1, 2);
        const float inv0 = 1.0f / sum0, inv1 = 1.0f / sum1;
        #pragma unroll
        for (int j = 0; j < 8; j++) {
            sacc[j][0] *= inv0; sacc[j][1] *= inv0;
            sacc[j][2] *= inv1; sacc[j][3] *= inv1;
        }

        float oacc[4][4];
        #pragma unroll
        for (int j = 0; j < 4; j++)
            #pragma unroll
            for (int e = 0; e < 4; e++) oacc[j][e] = 0.0f;

        #pragma unroll
        for (int ks = 0; ks < 4; ks++) {
            uint32_t ph[4];
            ph[0] = pack2h(sacc[2*ks][0],   sacc[2*ks][1]);
            ph[1] = pack2h(sacc[2*ks][2],   sacc[2*ks][3]);
            ph[2] = pack2h(sacc[2*ks+1][0], sacc[2*ks+1][1]);
            ph[3] = pack2h(sacc[2*ks+1][2], sacc[2*ks+1][3]);

            const uint32_t vrow = (uint32_t)(ks * 16 + (lane & 7)
                                  + ((lane >> 3) & 1) * 8) * ARS;
            #pragma unroll
            for (int dv = 0; dv < 2; dv++) {
                uint32_t Vh[4];
                const uint32_t voff = vrow
                    + (uint32_t)(dv * 16 + (lane >> 4) * 8) * 2;
                LDSM4T(Vh[0], Vh[1], Vh[2], Vh[3], vhB + voff);
                MMA16816(oacc[2*dv],   ph, &Vh[0]);
                MMA16816(oacc[2*dv+1], ph, &Vh[2]);
            }
        }

        {
            const size_t r0 = (size_t)(win * 64 + w * 16 + rr);
            const int colb = head * 32 + cc2;
            #pragma unroll
            for (int j = 0; j < 4; j++) {
                *(uint32_t*)(g_o + r0 * CC + colb + j * 8)
                    = pack2h(oacc[j][0], oacc[j][1]);
                *(uint32_t*)(g_o + (r0 + 8) * CC + colb + j * 8)
                    = pack2h(oacc[j][2], oacc[j][3]);
            }
        }

        if (h + 2 < NHCTA) {
            uint32_t nxt = stoff + 2 * ASTAGE;
            if (nxt >= ANSTG * ASTAGE) nxt -= ANSTG * ASTAGE;
            issue(h + 2, nxt);
        } else {
            CPCOMMIT();
        }
        CPWAIT(1);
        __syncthreads();

        stoff += ASTAGE;
        if (stoff == ANSTG * ASTAGE) stoff = 0;
    }
}

// ---------------------------------------------------------------------------
// launch: pre -> GEMM1 -> attn -> GEMM2 (4 launches; ncu slot -> GEMM2)
// ---------------------------------------------------------------------------
extern "C" void kernel_launch(void* const* d_in, const int* in_sizes, int n_in,
                              void* d_out, int out_size)
{
    const float* x       = (const float*)d_in[0];
    const float* w_qkv   = (const float*)d_in[1];
    const float* b_qkv   = (const float*)d_in[2];
    const float* rel_pos = (const float*)d_in[3];
    const float* w_out   = (const float*)d_in[4];
    const float* b_out   = (const float*)d_in[5];
    float* out = (float*)d_out;

    const int dyn = NSTG * STAGE;   // 61440
    cudaFuncSetAttribute(mma_gemm_kernel<0>,
                         cudaFuncAttributeMaxDynamicSharedMemorySize, dyn);
    cudaFuncSetAttribute(mma_gemm_kernel<1>,
                         cudaFuncAttributeMaxDynamicSharedMemorySize, dyn);
    const int adyn = ANSTG * ASTAGE; // 46080
    cudaFuncSetAttribute(attn_kernel,
                         cudaFuncAttributeMaxDynamicSharedMemorySize, adyn);

    pre_kernel<<<PRE_END, 256>>>(x, w_qkv, w_out, rel_pos);
    mma_gemm_kernel<0><<<dim3(NQKV / 128, MROWS / 128), 256, dyn>>>(b_qkv, nullptr);
    attn_kernel<<<dim3(1024, NHEAD / NHCTA), 128, adyn>>>();
    mma_gemm_kernel<1><<<dim3(CC / 128, MROWS / 128), 256, dyn>>>(b_out, out);
}